// round 2
// baseline (speedup 1.0000x reference)
#include <cuda_runtime.h>

#define D 128            // DH == DX == 128
#define MAX_M 4096
#define MAX_N 262144

// Scratch (no allocations allowed): proj matrix + segment offsets
__device__ float g_proj[MAX_M * D];
__device__ int   g_offsets[MAX_M + 1];

// ---------------------------------------------------------------------------
// Kernel 1: segment offsets from sorted segment_ids, int4-vectorized.
// offsets[g] = first node index of segment g; offsets[M] = N. Handles empty
// segments (their offset range collapses, start==end downstream).
// ---------------------------------------------------------------------------
__global__ void offsets_kernel(const int* __restrict__ seg, int n, int m) {
    int t = blockIdx.x * blockDim.x + threadIdx.x;   // handles ids [4t, 4t+4)
    int base = t * 4;
    if (base >= n) return;
    int4 v = ((const int4*)seg)[t];
    int prev = (base == 0) ? -1 : __ldg(&seg[base - 1]);

    int ids[4] = {v.x, v.y, v.z, v.w};
#pragma unroll
    for (int k = 0; k < 4; k++) {
        int s = ids[k];
        for (int g = prev + 1; g <= s; ++g) g_offsets[g] = base + k;
        prev = s;
    }
    if (base + 4 >= n) {
        for (int g = prev + 1; g <= m; ++g) g_offsets[g] = n;
    }
}

// ---------------------------------------------------------------------------
// Kernel 2: proj = h @ a   (M x 128) = (M x 128)(128 x 128)
// 128 blocks x 128 threads, 32 rows/block. Register tile R=8 x C=4.
// ---------------------------------------------------------------------------
__global__ __launch_bounds__(128) void proj_kernel(const float* __restrict__ h,
                                                   const float* __restrict__ a) {
    __shared__ float a_sh[64 * D];   // 32 KB (one k-half of a)
    __shared__ float h_sh[32 * D];   // 16 KB (row tile of h)

    int tid = threadIdx.x;
    int cg  = tid & 31;   // column group: 4 cols starting at cg*4
    int rg  = tid >> 5;   // row group: 8 rows starting at rg*8
    int rowBase = blockIdx.x * 32;

    const float4* h4 = (const float4*)h;
    const float4* a4 = (const float4*)a;
    float4* h_sh4 = (float4*)h_sh;
    float4* a_sh4 = (float4*)a_sh;

    for (int idx = tid; idx < 32 * (D / 4); idx += 128)
        h_sh4[idx] = h4[rowBase * (D / 4) + idx];

    float acc[8][4];
#pragma unroll
    for (int r = 0; r < 8; r++)
        acc[r][0] = acc[r][1] = acc[r][2] = acc[r][3] = 0.f;

    for (int half = 0; half < 2; half++) {
        __syncthreads();
        for (int idx = tid; idx < 64 * (D / 4); idx += 128)
            a_sh4[idx] = a4[half * 64 * (D / 4) + idx];
        __syncthreads();

#pragma unroll 4
        for (int k2 = 0; k2 < 64; k2++) {
            float4 av = *(const float4*)&a_sh[k2 * D + cg * 4];
            int k = half * 64 + k2;
#pragma unroll
            for (int r = 0; r < 8; r++) {
                float hv = h_sh[(rg * 8 + r) * D + k];
                acc[r][0] += hv * av.x;
                acc[r][1] += hv * av.y;
                acc[r][2] += hv * av.z;
                acc[r][3] += hv * av.w;
            }
        }
    }

    float4* p4 = (float4*)g_proj;
#pragma unroll
    for (int r = 0; r < 8; r++) {
        int row = rowBase + rg * 8 + r;
        p4[row * (D / 4) + cg] =
            make_float4(acc[r][0], acc[r][1], acc[r][2], acc[r][3]);
    }
}

// ---------------------------------------------------------------------------
// Kernel 3: one block per graph, SINGLE pass over x with online softmax.
// 8 warps; warp owns nodes start+w, start+w+8, ... Lane l holds cols 4l..4l+3.
// Per-warp running (m, z, acc) with branchless rescale; cross-warp flash
// combine in the epilogue. x is read from DRAM exactly once.
// ---------------------------------------------------------------------------
__device__ __forceinline__ float warp_dot(float4 v, float4 p) {
    float d = fmaf(v.x, p.x, fmaf(v.y, p.y, fmaf(v.z, p.z, v.w * p.w)));
    d += __shfl_xor_sync(0xffffffffu, d, 16);
    d += __shfl_xor_sync(0xffffffffu, d, 8);
    d += __shfl_xor_sync(0xffffffffu, d, 4);
    d += __shfl_xor_sync(0xffffffffu, d, 2);
    d += __shfl_xor_sync(0xffffffffu, d, 1);
    return d;   // all lanes hold the full dot product
}

__global__ __launch_bounds__(256) void attn_kernel(const float4* __restrict__ x4,
                                                   float* __restrict__ out) {
    int g     = blockIdx.x;
    int start = g_offsets[g];
    int end   = g_offsets[g + 1];
    int tid   = threadIdx.x;

    if (start >= end) {           // empty segment -> zeros (uniform branch)
        if (tid < D) out[g * D + tid] = 0.f;
        return;
    }

    int lane = tid & 31;
    int w    = tid >> 5;

    __shared__ float s_m[8];
    __shared__ float s_z[8];
    __shared__ float s_acc[8 * D];

    const float4* p4 = (const float4*)g_proj;
    float4 p = p4[g * 32 + lane];  // proj row resident in registers

    const float NEG_INF = -3.402823466e38f;
    float  m_w = NEG_INF;
    float  z_w = 0.f;
    float4 acc = make_float4(0.f, 0.f, 0.f, 0.f);

    int i = start + w;
    // ---- main loop: 2 nodes per iteration for load MLP ----
    for (; i + 8 < end; i += 16) {
        float4 v0 = x4[(size_t)i * 32 + lane];
        float4 v1 = x4[(size_t)(i + 8) * 32 + lane];
        float d0 = warp_dot(v0, p);
        float d1 = warp_dot(v1, p);
        float m_new = fmaxf(m_w, fmaxf(d0, d1));
        float c  = __expf(m_w - m_new);   // 0 on first iter (m_w = -inf)
        float e0 = __expf(d0 - m_new);
        float e1 = __expf(d1 - m_new);
        z_w   = fmaf(z_w, c, e0 + e1);
        acc.x = fmaf(acc.x, c, fmaf(e0, v0.x, e1 * v1.x));
        acc.y = fmaf(acc.y, c, fmaf(e0, v0.y, e1 * v1.y));
        acc.z = fmaf(acc.z, c, fmaf(e0, v0.z, e1 * v1.z));
        acc.w = fmaf(acc.w, c, fmaf(e0, v0.w, e1 * v1.w));
        m_w = m_new;
    }
    // ---- remainder (at most one node per warp) ----
    if (i < end) {
        float4 v = x4[(size_t)i * 32 + lane];
        float d  = warp_dot(v, p);
        float m_new = fmaxf(m_w, d);
        float c = __expf(m_w - m_new);
        float e = __expf(d - m_new);
        z_w   = fmaf(z_w, c, e);
        acc.x = fmaf(acc.x, c, e * v.x);
        acc.y = fmaf(acc.y, c, e * v.y);
        acc.z = fmaf(acc.z, c, e * v.z);
        acc.w = fmaf(acc.w, c, e * v.w);
        m_w = m_new;
    }

    if (lane == 0) { s_m[w] = m_w; s_z[w] = z_w; }
    ((float4*)s_acc)[w * 32 + lane] = acc;
    __syncthreads();

    // ---- epilogue: flash combine across 8 warps + normalize ----
    if (tid < D) {
        float mg = s_m[0];
#pragma unroll
        for (int j = 1; j < 8; j++) mg = fmaxf(mg, s_m[j]);
        float f[8];
        float z = 0.f;
#pragma unroll
        for (int j = 0; j < 8; j++) {
            f[j] = __expf(s_m[j] - mg);   // 0 for idle warps (m = -inf)
            z = fmaf(s_z[j], f[j], z);
        }
        float v = 0.f;
#pragma unroll
        for (int j = 0; j < 8; j++) v = fmaf(s_acc[j * D + tid], f[j], v);
        out[g * D + tid] = v / z;
    }
}

// ---------------------------------------------------------------------------
// Launch: inputs per metadata order: h (M*128 f32), x (N*128 f32),
// a (128*128 f32), segment_ids (N int32). Output: M*128 f32.
// ---------------------------------------------------------------------------
extern "C" void kernel_launch(void* const* d_in, const int* in_sizes, int n_in,
                              void* d_out, int out_size) {
    const float* h   = (const float*)d_in[0];
    const float* x   = (const float*)d_in[1];
    const float* a   = (const float*)d_in[2];
    const int*   seg = (const int*)d_in[3];
    float* out = (float*)d_out;

    int m = in_sizes[0] / D;   // 4096
    int n = in_sizes[3];       // 262144

    int n4 = (n + 3) / 4;
    offsets_kernel<<<(n4 + 255) / 256, 256>>>(seg, n, m);
    proj_kernel<<<m / 32, 128>>>(h, a);
    attn_kernel<<<m, 256>>>((const float4*)x, out);
}

// round 3
// speedup vs baseline: 1.2319x; 1.2319x over previous
#include <cuda_runtime.h>

#define D 128            // DH == DX == 128
#define MAX_M 4096
#define MAX_N 262144

#define PROJ_BLOCKS 256      // 16 rows each -> 4096 rows
#define PROJ_ROWS   16

// Scratch (no allocations allowed): proj matrix + segment offsets
__device__ float g_proj[MAX_M * D];
__device__ int   g_offsets[MAX_M + 1];

// ---------------------------------------------------------------------------
// Kernel A (fused): blocks [0, PROJ_BLOCKS) compute proj = h @ a;
// blocks [PROJ_BLOCKS, ...) compute segment offsets from sorted segment_ids.
// The two jobs are independent and overlap inside one launch.
// ---------------------------------------------------------------------------
__global__ __launch_bounds__(256) void pre_kernel(const float* __restrict__ h,
                                                  const float* __restrict__ a,
                                                  const int* __restrict__ seg,
                                                  int n, int m) {
    __shared__ float a_sh[64 * D];          // 32 KB (one k-half of a)
    __shared__ float h_sh[PROJ_ROWS * D];   // 8 KB

    int tid = threadIdx.x;

    if (blockIdx.x < PROJ_BLOCKS) {
        // ---------------- proj = h @ a, 16 rows per block ----------------
        int cg = tid & 31;   // 4 cols starting at cg*4
        int rg = tid >> 5;   // 2 rows starting at rg*2
        int rowBase = blockIdx.x * PROJ_ROWS;

        const float4* h4 = (const float4*)h;
        const float4* a4 = (const float4*)a;
        float4* h_sh4 = (float4*)h_sh;
        float4* a_sh4 = (float4*)a_sh;

        for (int idx = tid; idx < PROJ_ROWS * (D / 4); idx += 256)
            h_sh4[idx] = h4[rowBase * (D / 4) + idx];

        float acc[2][4];
#pragma unroll
        for (int r = 0; r < 2; r++)
            acc[r][0] = acc[r][1] = acc[r][2] = acc[r][3] = 0.f;

        for (int half = 0; half < 2; half++) {
            __syncthreads();
            for (int idx = tid; idx < 64 * (D / 4); idx += 256)
                a_sh4[idx] = a4[half * 64 * (D / 4) + idx];
            __syncthreads();

#pragma unroll 8
            for (int k2 = 0; k2 < 64; k2++) {
                float4 av = *(const float4*)&a_sh[k2 * D + cg * 4];
                int k = half * 64 + k2;
#pragma unroll
                for (int r = 0; r < 2; r++) {
                    float hv = h_sh[(rg * 2 + r) * D + k];  // uniform: broadcast
                    acc[r][0] = fmaf(hv, av.x, acc[r][0]);
                    acc[r][1] = fmaf(hv, av.y, acc[r][1]);
                    acc[r][2] = fmaf(hv, av.z, acc[r][2]);
                    acc[r][3] = fmaf(hv, av.w, acc[r][3]);
                }
            }
        }

        float4* p4 = (float4*)g_proj;
#pragma unroll
        for (int r = 0; r < 2; r++) {
            int row = rowBase + rg * 2 + r;
            p4[row * (D / 4) + cg] =
                make_float4(acc[r][0], acc[r][1], acc[r][2], acc[r][3]);
        }
    } else {
        // ---------------- segment offsets (int4 per thread) ----------------
        int t = (blockIdx.x - PROJ_BLOCKS) * 256 + tid;   // ids [4t, 4t+4)
        int base = t * 4;
        if (base >= n) return;
        int4 v = ((const int4*)seg)[t];
        int prev = (base == 0) ? -1 : __ldg(&seg[base - 1]);

        int ids[4] = {v.x, v.y, v.z, v.w};
#pragma unroll
        for (int k = 0; k < 4; k++) {
            int s = ids[k];
            for (int g = prev + 1; g <= s; ++g) g_offsets[g] = base + k;
            prev = s;
        }
        if (base + 4 >= n) {
            for (int g = prev + 1; g <= m; ++g) g_offsets[g] = n;
        }
    }
}

// ---------------------------------------------------------------------------
// Kernel B: WARP-PER-GRAPH online-softmax attention.
// Each warp owns one whole graph (contiguous node range). Lane l holds
// columns 4l..4l+3 of both proj row and the accumulator. Main loop processes
// 4 nodes per iteration (4 independent dot/shfl chains in flight).
// No cross-warp combine, no __syncthreads, epilogue = 1 STG.128 per lane.
// ---------------------------------------------------------------------------
__device__ __forceinline__ float warp_dot(float4 v, float4 p) {
    float d = fmaf(v.x, p.x, fmaf(v.y, p.y, fmaf(v.z, p.z, v.w * p.w)));
    d += __shfl_xor_sync(0xffffffffu, d, 16);
    d += __shfl_xor_sync(0xffffffffu, d, 8);
    d += __shfl_xor_sync(0xffffffffu, d, 4);
    d += __shfl_xor_sync(0xffffffffu, d, 2);
    d += __shfl_xor_sync(0xffffffffu, d, 1);
    return d;   // all lanes hold the full dot product
}

__global__ __launch_bounds__(256) void attn_kernel(const float4* __restrict__ x4,
                                                   float* __restrict__ out,
                                                   int m) {
    int lane = threadIdx.x & 31;
    int w    = threadIdx.x >> 5;
    int g    = blockIdx.x * 8 + w;
    if (g >= m) return;

    int start = g_offsets[g];
    int end   = g_offsets[g + 1];

    float4* out4 = (float4*)out;
    if (start >= end) {                    // empty segment -> zeros
        out4[g * 32 + lane] = make_float4(0.f, 0.f, 0.f, 0.f);
        return;
    }

    const float4* p4 = (const float4*)g_proj;
    float4 p = p4[g * 32 + lane];          // proj row in registers

    const float NEG_INF = -3.402823466e38f;
    float  m_w = NEG_INF;
    float  z_w = 0.f;
    float4 acc = make_float4(0.f, 0.f, 0.f, 0.f);

    int i = start;
    // ---- main loop: 4 nodes per iteration ----
    for (; i + 4 <= end; i += 4) {
        const float4* b = x4 + (size_t)i * 32 + lane;
        float4 v0 = b[0];
        float4 v1 = b[32];
        float4 v2 = b[64];
        float4 v3 = b[96];
        float d0 = warp_dot(v0, p);
        float d1 = warp_dot(v1, p);
        float d2 = warp_dot(v2, p);
        float d3 = warp_dot(v3, p);
        float m_new = fmaxf(fmaxf(m_w, fmaxf(d0, d1)), fmaxf(d2, d3));
        float c  = __expf(m_w - m_new);    // 0 on first iteration
        float e0 = __expf(d0 - m_new);
        float e1 = __expf(d1 - m_new);
        float e2 = __expf(d2 - m_new);
        float e3 = __expf(d3 - m_new);
        z_w   = fmaf(z_w, c, (e0 + e1) + (e2 + e3));
        acc.x = fmaf(acc.x, c, fmaf(e0, v0.x, fmaf(e1, v1.x, fmaf(e2, v2.x, e3 * v3.x))));
        acc.y = fmaf(acc.y, c, fmaf(e0, v0.y, fmaf(e1, v1.y, fmaf(e2, v2.y, e3 * v3.y))));
        acc.z = fmaf(acc.z, c, fmaf(e0, v0.z, fmaf(e1, v1.z, fmaf(e2, v2.z, e3 * v3.z))));
        acc.w = fmaf(acc.w, c, fmaf(e0, v0.w, fmaf(e1, v1.w, fmaf(e2, v2.w, e3 * v3.w))));
        m_w = m_new;
    }
    // ---- remainder (up to 3 nodes) ----
    for (; i < end; ++i) {
        float4 v = x4[(size_t)i * 32 + lane];
        float d  = warp_dot(v, p);
        float m_new = fmaxf(m_w, d);
        float c = __expf(m_w - m_new);
        float e = __expf(d - m_new);
        z_w   = fmaf(z_w, c, e);
        acc.x = fmaf(acc.x, c, e * v.x);
        acc.y = fmaf(acc.y, c, e * v.y);
        acc.z = fmaf(acc.z, c, e * v.z);
        acc.w = fmaf(acc.w, c, e * v.w);
        m_w = m_new;
    }

    float inv = 1.f / z_w;
    out4[g * 32 + lane] =
        make_float4(acc.x * inv, acc.y * inv, acc.z * inv, acc.w * inv);
}

// ---------------------------------------------------------------------------
// Launch: inputs per metadata order: h (M*128 f32), x (N*128 f32),
// a (128*128 f32), segment_ids (N int32). Output: M*128 f32.
// ---------------------------------------------------------------------------
extern "C" void kernel_launch(void* const* d_in, const int* in_sizes, int n_in,
                              void* d_out, int out_size) {
    const float* h   = (const float*)d_in[0];
    const float* x   = (const float*)d_in[1];
    const float* a   = (const float*)d_in[2];
    const int*   seg = (const int*)d_in[3];
    float* out = (float*)d_out;

    int m = in_sizes[0] / D;   // 4096
    int n = in_sizes[3];       // 262144

    int n4 = (n + 3) / 4;
    int off_blocks = (n4 + 255) / 256;            // 64 ids per thread-block*? 256 thr * 4 ids
    pre_kernel<<<PROJ_BLOCKS + off_blocks, 256>>>(h, a, seg, n, m);
    attn_kernel<<<(m + 7) / 8, 256>>>((const float4*)x, out, m);
}